// round 1
// baseline (speedup 1.0000x reference)
#include <cuda_runtime.h>
#include <cuda_bf16.h>

#define NN 50000
#define EE 800000
#define DD 128

// ---------------- device scratch (no allocs allowed) ----------------
__device__ float4 g_h[NN * 32];      // current layer input (already * norm_src)
__device__ float4 g_agg[NN * 32];    // SpMM output (already * norm_dst)
__device__ int    g_deg_out[NN];
__device__ int    g_deg_in[NN];
__device__ float  g_norm_src[NN];
__device__ float  g_norm_dst[NN];
__device__ int    g_row_ptr[NN + 1];
__device__ int    g_cursor[NN];
__device__ int    g_col[EE];         // src ids grouped by dst

// ---------------- small setup kernels ----------------
__global__ void k_zero_deg() {
    int i = blockIdx.x * blockDim.x + threadIdx.x;
    if (i < NN) { g_deg_out[i] = 0; g_deg_in[i] = 0; }
}

__global__ void k_degree(const int* __restrict__ src, const int* __restrict__ dst) {
    int e = blockIdx.x * blockDim.x + threadIdx.x;
    if (e < EE) {
        atomicAdd(&g_deg_out[src[e]], 1);
        atomicAdd(&g_deg_in[dst[e]], 1);
    }
}

// single-block exclusive scan of deg_in -> row_ptr (+ cursor copy)
__global__ void k_scan() {
    __shared__ int warp_sums[32];
    __shared__ int s_carry;
    const int tid = threadIdx.x;
    if (tid == 0) s_carry = 0;
    __syncthreads();
    for (int base = 0; base < NN; base += 1024) {
        int i = base + tid;
        int v = (i < NN) ? g_deg_in[i] : 0;
        int x = v;
        #pragma unroll
        for (int off = 1; off < 32; off <<= 1) {
            int y = __shfl_up_sync(0xffffffffu, x, off);
            if ((tid & 31) >= off) x += y;
        }
        if ((tid & 31) == 31) warp_sums[tid >> 5] = x;
        __syncthreads();
        if (tid < 32) {
            int w = warp_sums[tid];
            #pragma unroll
            for (int off = 1; off < 32; off <<= 1) {
                int y = __shfl_up_sync(0xffffffffu, w, off);
                if (tid >= off) w += y;
            }
            warp_sums[tid] = w;  // inclusive over warps
        }
        __syncthreads();
        int warp_off = (tid >= 32) ? warp_sums[(tid >> 5) - 1] : 0;
        int incl = x + warp_off;
        int excl = incl - v + s_carry;
        if (i < NN) { g_row_ptr[i] = excl; g_cursor[i] = excl; }
        __syncthreads();
        if (tid == 1023) s_carry += incl;   // incl of last thread == tile total
        __syncthreads();
    }
    if (tid == 0) g_row_ptr[NN] = s_carry;
}

__global__ void k_fill(const int* __restrict__ src, const int* __restrict__ dst) {
    int e = blockIdx.x * blockDim.x + threadIdx.x;
    if (e < EE) {
        int d = dst[e];
        int p = atomicAdd(&g_cursor[d], 1);
        g_col[p] = src[e];
    }
}

// h0 = emb[batch] * norm_src ; also stash norms
__global__ void k_h0(const int* __restrict__ batch, const float4* __restrict__ emb) {
    int idx = blockIdx.x * blockDim.x + threadIdx.x;
    if (idx >= NN * 32) return;
    int i = idx >> 5, q = idx & 31;
    int dout = g_deg_out[i]; if (dout < 1) dout = 1;
    float ns = rsqrtf((float)dout);
    float4 v = emb[(size_t)batch[i] * 32 + q];
    v.x *= ns; v.y *= ns; v.z *= ns; v.w *= ns;
    g_h[idx] = v;
    if (q == 0) {
        g_norm_src[i] = ns;
        int din = g_deg_in[i]; if (din < 1) din = 1;
        g_norm_dst[i] = rsqrtf((float)din);
    }
}

// ---------------- SpMM: pull-style, warp per dst node ----------------
__global__ void k_spmm() {
    int warp = (blockIdx.x * blockDim.x + threadIdx.x) >> 5;
    int lane = threadIdx.x & 31;
    if (warp >= NN) return;
    int beg = g_row_ptr[warp];
    int end = g_row_ptr[warp + 1];
    float4 acc = make_float4(0.f, 0.f, 0.f, 0.f);
    for (int j0 = beg; j0 < end; j0 += 32) {
        int c = 0;
        if (j0 + lane < end) c = g_col[j0 + lane];
        int n = end - j0; if (n > 32) n = 32;
        int t = 0;
        for (; t + 3 < n; t += 4) {
            int s0 = __shfl_sync(0xffffffffu, c, t);
            int s1 = __shfl_sync(0xffffffffu, c, t + 1);
            int s2 = __shfl_sync(0xffffffffu, c, t + 2);
            int s3 = __shfl_sync(0xffffffffu, c, t + 3);
            float4 v0 = g_h[s0 * 32 + lane];
            float4 v1 = g_h[s1 * 32 + lane];
            float4 v2 = g_h[s2 * 32 + lane];
            float4 v3 = g_h[s3 * 32 + lane];
            acc.x += v0.x + v1.x + v2.x + v3.x;
            acc.y += v0.y + v1.y + v2.y + v3.y;
            acc.z += v0.z + v1.z + v2.z + v3.z;
            acc.w += v0.w + v1.w + v2.w + v3.w;
        }
        for (; t < n; t++) {
            int s = __shfl_sync(0xffffffffu, c, t);
            float4 v = g_h[s * 32 + lane];
            acc.x += v.x; acc.y += v.y; acc.z += v.z; acc.w += v.w;
        }
    }
    float nd = g_norm_dst[warp];
    acc.x *= nd; acc.y *= nd; acc.z *= nd; acc.w *= nd;
    g_agg[warp * 32 + lane] = acc;
}

// ---------------- fp32 GEMM: out = act(A @ W + b) [* rowscale] ----------------
// A: M x 128 row-major, W: 128 x 128 row-major. 128x128 block tile, 8x8/thread.
__global__ __launch_bounds__(256) void k_gemm(
    const float4* __restrict__ A, const float* __restrict__ W,
    const float* __restrict__ bias, const float* __restrict__ rowscale,
    float4* __restrict__ out, int M)
{
    __shared__ float As[16][128];   // As[k][m]
    __shared__ float Bs[16][128];   // Bs[k][n]
    const int tid = threadIdx.x;
    const int tx = tid & 15;        // col group (8 cols)
    const int ty = tid >> 4;        // row group (8 rows)
    const int row0 = blockIdx.x * 128;

    float acc[8][8];
    #pragma unroll
    for (int i = 0; i < 8; i++)
        #pragma unroll
        for (int j = 0; j < 8; j++) acc[i][j] = 0.f;

    const float4* W4 = (const float4*)W;

    for (int k0 = 0; k0 < 128; k0 += 16) {
        // A tile: 128 rows x 16 k, transposed into As[k][m]
        #pragma unroll
        for (int l = 0; l < 2; l++) {
            int idx = tid + l * 256;   // 0..511
            int m   = idx >> 2;        // 0..127
            int kq  = idx & 3;         // float4 within k range
            int gr  = row0 + m;
            float4 v = (gr < M) ? A[gr * 32 + (k0 >> 2) + kq]
                                : make_float4(0.f, 0.f, 0.f, 0.f);
            As[kq * 4 + 0][m] = v.x;
            As[kq * 4 + 1][m] = v.y;
            As[kq * 4 + 2][m] = v.z;
            As[kq * 4 + 3][m] = v.w;
        }
        // B tile: 16 k x 128 n
        #pragma unroll
        for (int l = 0; l < 2; l++) {
            int idx = tid + l * 256;   // 0..511
            int k   = idx >> 5;        // 0..15
            int nq  = idx & 31;
            float4 v = __ldg(W4 + (size_t)(k0 + k) * 32 + nq);
            *(float4*)&Bs[k][nq * 4] = v;
        }
        __syncthreads();
        #pragma unroll
        for (int k = 0; k < 16; k++) {
            float4 a0 = *(const float4*)&As[k][ty * 8];
            float4 a1 = *(const float4*)&As[k][ty * 8 + 4];
            float4 w0 = *(const float4*)&Bs[k][tx * 8];
            float4 w1 = *(const float4*)&Bs[k][tx * 8 + 4];
            float a[8] = {a0.x, a0.y, a0.z, a0.w, a1.x, a1.y, a1.z, a1.w};
            float w[8] = {w0.x, w0.y, w0.z, w0.w, w1.x, w1.y, w1.z, w1.w};
            #pragma unroll
            for (int i = 0; i < 8; i++)
                #pragma unroll
                for (int j = 0; j < 8; j++)
                    acc[i][j] += a[i] * w[j];
        }
        __syncthreads();
    }

    float bcol[8];
    #pragma unroll
    for (int j = 0; j < 8; j++) bcol[j] = bias[tx * 8 + j];

    #pragma unroll
    for (int i = 0; i < 8; i++) {
        int gr = row0 + ty * 8 + i;
        if (gr < M) {
            float rs = rowscale ? rowscale[gr] : 1.0f;
            float4 o0, o1;
            o0.x = fmaxf(acc[i][0] + bcol[0], 0.f) * rs;
            o0.y = fmaxf(acc[i][1] + bcol[1], 0.f) * rs;
            o0.z = fmaxf(acc[i][2] + bcol[2], 0.f) * rs;
            o0.w = fmaxf(acc[i][3] + bcol[3], 0.f) * rs;
            o1.x = fmaxf(acc[i][4] + bcol[4], 0.f) * rs;
            o1.y = fmaxf(acc[i][5] + bcol[5], 0.f) * rs;
            o1.z = fmaxf(acc[i][6] + bcol[6], 0.f) * rs;
            o1.w = fmaxf(acc[i][7] + bcol[7], 0.f) * rs;
            out[gr * 32 + tx * 2]     = o0;
            out[gr * 32 + tx * 2 + 1] = o1;
        }
    }
}

// ---------------- launch ----------------
extern "C" void kernel_launch(void* const* d_in, const int* in_sizes, int n_in,
                              void* d_out, int out_size)
{
    const int*   batch = (const int*)d_in[0];
    const int*   src   = (const int*)d_in[1];
    const int*   dst   = (const int*)d_in[2];
    const float* emb   = (const float*)d_in[3];
    const float* W1    = (const float*)d_in[4];
    const float* b1    = (const float*)d_in[5];
    const float* W2    = (const float*)d_in[6];
    const float* b2    = (const float*)d_in[7];
    const float* W3    = (const float*)d_in[8];
    const float* b3    = (const float*)d_in[9];
    float* outp = (float*)d_out;

    float4* hbuf;   cudaGetSymbolAddress((void**)&hbuf, g_h);
    float4* aggbuf; cudaGetSymbolAddress((void**)&aggbuf, g_agg);
    float* nsrc;    cudaGetSymbolAddress((void**)&nsrc, g_norm_src);

    k_zero_deg<<<(NN + 255) / 256, 256>>>();
    k_degree<<<(EE + 255) / 256, 256>>>(src, dst);
    k_scan<<<1, 1024>>>();
    k_fill<<<(EE + 255) / 256, 256>>>(src, dst);
    k_h0<<<(NN * 32 + 255) / 256, 256>>>(batch, (const float4*)emb);

    const int gemm_grid = (NN + 127) / 128;
    const int spmm_grid = (NN + 7) / 8;

    // layer 1
    k_spmm<<<spmm_grid, 256>>>();
    k_gemm<<<gemm_grid, 256>>>(aggbuf, W1, b1, nsrc, hbuf, NN);
    // layer 2
    k_spmm<<<spmm_grid, 256>>>();
    k_gemm<<<gemm_grid, 256>>>(aggbuf, W2, b2, nsrc, hbuf, NN);
    // layer 3 -> d_out (no rowscale)
    k_spmm<<<spmm_grid, 256>>>();
    k_gemm<<<gemm_grid, 256>>>(aggbuf, W3, b3, nullptr, (float4*)outp, NN);
}

// round 2
// speedup vs baseline: 1.7164x; 1.7164x over previous
#include <cuda_runtime.h>
#include <cuda_bf16.h>

#define NN 50000
#define EE 800000
#define DD 128

// ---------------- device scratch (no allocs allowed) ----------------
__device__ float4 g_h[NN * 32];      // current layer input (already * norm_src)
__device__ float4 g_agg[NN * 32];    // SpMM output (already * norm_dst)
__device__ int    g_deg_out[NN];
__device__ int    g_deg_in[NN];
__device__ float  g_norm_src[NN];
__device__ float  g_norm_dst[NN];
__device__ int    g_row_ptr[NN + 1];
__device__ int    g_cursor[NN];
__device__ int    g_col[EE];         // src ids grouped by dst
__device__ int    g_bsum[64];
__device__ int    g_boff[64];

// ---------------- small setup kernels ----------------
__global__ void k_zero_deg() {
    int i = blockIdx.x * blockDim.x + threadIdx.x;
    if (i < NN) { g_deg_out[i] = 0; g_deg_in[i] = 0; }
}

__global__ void k_degree(const int* __restrict__ src, const int* __restrict__ dst) {
    int e = blockIdx.x * blockDim.x + threadIdx.x;
    if (e < EE) {
        atomicAdd(&g_deg_out[src[e]], 1);
        atomicAdd(&g_deg_in[dst[e]], 1);
    }
}

// phase 1: per-block exclusive scan of deg_in (1024/block), block sums out
__global__ void k_scan1() {
    __shared__ int warp_sums[32];
    const int tid = threadIdx.x;
    int i = blockIdx.x * 1024 + tid;
    int v = (i < NN) ? g_deg_in[i] : 0;
    int x = v;
    #pragma unroll
    for (int off = 1; off < 32; off <<= 1) {
        int y = __shfl_up_sync(0xffffffffu, x, off);
        if ((tid & 31) >= off) x += y;
    }
    if ((tid & 31) == 31) warp_sums[tid >> 5] = x;
    __syncthreads();
    if (tid < 32) {
        int w = warp_sums[tid];
        #pragma unroll
        for (int off = 1; off < 32; off <<= 1) {
            int y = __shfl_up_sync(0xffffffffu, w, off);
            if (tid >= off) w += y;
        }
        warp_sums[tid] = w;  // inclusive over warps
    }
    __syncthreads();
    int warp_off = (tid >= 32) ? warp_sums[(tid >> 5) - 1] : 0;
    int incl = x + warp_off;
    if (i < NN) g_row_ptr[i] = incl - v;       // local exclusive
    if (tid == 1023) g_bsum[blockIdx.x] = incl;
}

// phase 2: exclusive scan of 49 block sums (single block, 64 threads)
__global__ void k_scan2(int nblocks) {
    __shared__ int s[64];
    int tid = threadIdx.x;
    int v = (tid < nblocks) ? g_bsum[tid] : 0;
    int x = v;
    #pragma unroll
    for (int off = 1; off < 32; off <<= 1) {
        int y = __shfl_up_sync(0xffffffffu, x, off);
        if ((tid & 31) >= off) x += y;
    }
    if ((tid & 31) == 31) s[tid >> 5] = x;
    __syncthreads();
    int carry = (tid >= 32) ? s[0] : 0;
    g_boff[tid] = x - v + carry;
}

// phase 3: add block offsets, init cursor, finalize row_ptr[NN]
__global__ void k_scan3() {
    int i = blockIdx.x * blockDim.x + threadIdx.x;
    if (i < NN) {
        int val = g_row_ptr[i] + g_boff[i >> 10];
        g_row_ptr[i] = val;
        g_cursor[i]  = val;
    }
    if (i == 0) g_row_ptr[NN] = EE;
}

__global__ void k_fill(const int* __restrict__ src, const int* __restrict__ dst) {
    int e = blockIdx.x * blockDim.x + threadIdx.x;
    if (e < EE) {
        int d = dst[e];
        int p = atomicAdd(&g_cursor[d], 1);
        g_col[p] = src[e];
    }
}

// h0 = emb[batch] * norm_src ; also stash norms
__global__ void k_h0(const int* __restrict__ batch, const float4* __restrict__ emb) {
    int idx = blockIdx.x * blockDim.x + threadIdx.x;
    if (idx >= NN * 32) return;
    int i = idx >> 5, q = idx & 31;
    int dout = g_deg_out[i]; if (dout < 1) dout = 1;
    float ns = rsqrtf((float)dout);
    float4 v = emb[(size_t)batch[i] * 32 + q];
    v.x *= ns; v.y *= ns; v.z *= ns; v.w *= ns;
    g_h[idx] = v;
    if (q == 0) {
        g_norm_src[i] = ns;
        int din = g_deg_in[i]; if (din < 1) din = 1;
        g_norm_dst[i] = rsqrtf((float)din);
    }
}

// ---------------- SpMM: pull-style, warp per dst node ----------------
__global__ void k_spmm() {
    int warp = (blockIdx.x * blockDim.x + threadIdx.x) >> 5;
    int lane = threadIdx.x & 31;
    if (warp >= NN) return;
    int beg = g_row_ptr[warp];
    int end = g_row_ptr[warp + 1];
    float4 acc = make_float4(0.f, 0.f, 0.f, 0.f);
    for (int j0 = beg; j0 < end; j0 += 32) {
        int c = 0;
        if (j0 + lane < end) c = g_col[j0 + lane];
        int n = end - j0; if (n > 32) n = 32;
        int t = 0;
        for (; t + 3 < n; t += 4) {
            int s0 = __shfl_sync(0xffffffffu, c, t);
            int s1 = __shfl_sync(0xffffffffu, c, t + 1);
            int s2 = __shfl_sync(0xffffffffu, c, t + 2);
            int s3 = __shfl_sync(0xffffffffu, c, t + 3);
            float4 v0 = g_h[s0 * 32 + lane];
            float4 v1 = g_h[s1 * 32 + lane];
            float4 v2 = g_h[s2 * 32 + lane];
            float4 v3 = g_h[s3 * 32 + lane];
            acc.x += v0.x + v1.x + v2.x + v3.x;
            acc.y += v0.y + v1.y + v2.y + v3.y;
            acc.z += v0.z + v1.z + v2.z + v3.z;
            acc.w += v0.w + v1.w + v2.w + v3.w;
        }
        for (; t < n; t++) {
            int s = __shfl_sync(0xffffffffu, c, t);
            float4 v = g_h[s * 32 + lane];
            acc.x += v.x; acc.y += v.y; acc.z += v.z; acc.w += v.w;
        }
    }
    float nd = g_norm_dst[warp];
    acc.x *= nd; acc.y *= nd; acc.z *= nd; acc.w *= nd;
    g_agg[warp * 32 + lane] = acc;
}

// ---------------- TF32 tensor-core GEMM ----------------
// out = relu(A @ W + b) [* rowscale].  A: M x 128 (float4 rows of 32), W: 128x128.
// Block: 128x128 tile, 8 warps in 4x2 (each warp 32 rows x 64 cols), Ktile=64.
__device__ __forceinline__ unsigned f2tf(float f) {
    unsigned u;
    asm("cvt.rna.tf32.f32 %0, %1;" : "=r"(u) : "f"(f));
    return u;
}

#define AS_STRIDE 68
#define BS_STRIDE 136
#define GEMM_SMEM ((128 * AS_STRIDE + 64 * BS_STRIDE) * 4)

__global__ __launch_bounds__(256, 2) void k_gemm_tf32(
    const float4* __restrict__ A, const float4* __restrict__ W4,
    const float* __restrict__ bias, const float* __restrict__ rowscale,
    float2* __restrict__ out, int M)
{
    extern __shared__ unsigned smem[];
    unsigned* As = smem;                       // [128][68]
    unsigned* Bs = smem + 128 * AS_STRIDE;     // [64][136]

    const int tid  = threadIdx.x;
    const int wid  = tid >> 5;
    const int lane = tid & 31;
    const int g = lane >> 2;       // 0..7
    const int c = lane & 3;        // 0..3
    const int wm = (wid & 3) * 32; // warp row offset in tile
    const int wn = (wid >> 2) * 64;// warp col offset in tile
    const int row0 = blockIdx.x * 128;

    float acc[2][8][4];
    #pragma unroll
    for (int i = 0; i < 2; i++)
        #pragma unroll
        for (int j = 0; j < 8; j++)
            #pragma unroll
            for (int k = 0; k < 4; k++) acc[i][j][k] = 0.f;

    for (int k0 = 0; k0 < 128; k0 += 64) {
        // A tile: 128 rows x 64 cols (tf32 converted)
        #pragma unroll
        for (int l = 0; l < 8; l++) {
            int idx = l * 256 + tid;     // 0..2047
            int r = idx >> 4;            // 0..127
            int q = idx & 15;            // float4 within chunk
            float4 v = (row0 + r < M) ? A[(row0 + r) * 32 + (k0 >> 2) + q]
                                      : make_float4(0.f, 0.f, 0.f, 0.f);
            uint4 t = make_uint4(f2tf(v.x), f2tf(v.y), f2tf(v.z), f2tf(v.w));
            *(uint4*)&As[r * AS_STRIDE + q * 4] = t;
        }
        // B tile: 64 k x 128 n
        #pragma unroll
        for (int l = 0; l < 8; l++) {
            int idx = l * 256 + tid;
            int k = idx >> 5;            // 0..63
            int nq = idx & 31;
            float4 v = __ldg(&W4[(size_t)(k0 + k) * 32 + nq]);
            uint4 t = make_uint4(f2tf(v.x), f2tf(v.y), f2tf(v.z), f2tf(v.w));
            *(uint4*)&Bs[k * BS_STRIDE + nq * 4] = t;
        }
        __syncthreads();

        #pragma unroll
        for (int kk = 0; kk < 64; kk += 8) {
            unsigned a[2][4];
            #pragma unroll
            for (int mt = 0; mt < 2; mt++) {
                int r = wm + mt * 16 + g;
                a[mt][0] = As[r * AS_STRIDE + kk + c];
                a[mt][1] = As[(r + 8) * AS_STRIDE + kk + c];
                a[mt][2] = As[r * AS_STRIDE + kk + c + 4];
                a[mt][3] = As[(r + 8) * AS_STRIDE + kk + c + 4];
            }
            #pragma unroll
            for (int nt = 0; nt < 8; nt++) {
                unsigned b0 = Bs[(kk + c) * BS_STRIDE + wn + nt * 8 + g];
                unsigned b1 = Bs[(kk + c + 4) * BS_STRIDE + wn + nt * 8 + g];
                #pragma unroll
                for (int mt = 0; mt < 2; mt++) {
                    asm volatile(
                        "mma.sync.aligned.m16n8k8.row.col.f32.tf32.tf32.f32 "
                        "{%0,%1,%2,%3}, {%4,%5,%6,%7}, {%8,%9}, {%0,%1,%2,%3};\n"
                        : "+f"(acc[mt][nt][0]), "+f"(acc[mt][nt][1]),
                          "+f"(acc[mt][nt][2]), "+f"(acc[mt][nt][3])
                        : "r"(a[mt][0]), "r"(a[mt][1]), "r"(a[mt][2]), "r"(a[mt][3]),
                          "r"(b0), "r"(b1));
                }
            }
        }
        __syncthreads();
    }

    // epilogue: bias + relu (+ rowscale), write float2 pairs
    const int c2 = c * 2;
    #pragma unroll
    for (int nt = 0; nt < 8; nt++) {
        int col = wn + nt * 8 + c2;
        float bi0 = bias[col], bi1 = bias[col + 1];
        #pragma unroll
        for (int mt = 0; mt < 2; mt++) {
            int r = row0 + wm + mt * 16 + g;
            if (r < M) {
                float rs = rowscale ? rowscale[r] : 1.0f;
                float2 o;
                o.x = fmaxf(acc[mt][nt][0] + bi0, 0.f) * rs;
                o.y = fmaxf(acc[mt][nt][1] + bi1, 0.f) * rs;
                out[r * 64 + (col >> 1)] = o;
            }
            int r2 = r + 8;
            if (r2 < M) {
                float rs = rowscale ? rowscale[r2] : 1.0f;
                float2 o;
                o.x = fmaxf(acc[mt][nt][2] + bi0, 0.f) * rs;
                o.y = fmaxf(acc[mt][nt][3] + bi1, 0.f) * rs;
                out[r2 * 64 + (col >> 1)] = o;
            }
        }
    }
}

// ---------------- launch ----------------
extern "C" void kernel_launch(void* const* d_in, const int* in_sizes, int n_in,
                              void* d_out, int out_size)
{
    const int*   batch = (const int*)d_in[0];
    const int*   src   = (const int*)d_in[1];
    const int*   dst   = (const int*)d_in[2];
    const float* emb   = (const float*)d_in[3];
    const float* W1    = (const float*)d_in[4];
    const float* b1    = (const float*)d_in[5];
    const float* W2    = (const float*)d_in[6];
    const float* b2    = (const float*)d_in[7];
    const float* W3    = (const float*)d_in[8];
    const float* b3    = (const float*)d_in[9];
    float* outp = (float*)d_out;

    float4* hbuf;   cudaGetSymbolAddress((void**)&hbuf, g_h);
    float4* aggbuf; cudaGetSymbolAddress((void**)&aggbuf, g_agg);
    float* nsrc;    cudaGetSymbolAddress((void**)&nsrc, g_norm_src);

    cudaFuncSetAttribute(k_gemm_tf32, cudaFuncAttributeMaxDynamicSharedMemorySize,
                         GEMM_SMEM);

    const int scan_blocks = (NN + 1023) / 1024;   // 49

    k_zero_deg<<<(NN + 255) / 256, 256>>>();
    k_degree<<<(EE + 255) / 256, 256>>>(src, dst);
    k_scan1<<<scan_blocks, 1024>>>();
    k_scan2<<<1, 64>>>(scan_blocks);
    k_scan3<<<(NN + 255) / 256, 256>>>();
    k_fill<<<(EE + 255) / 256, 256>>>(src, dst);
    k_h0<<<(NN * 32 + 255) / 256, 256>>>(batch, (const float4*)emb);

    const int gemm_grid = (NN + 127) / 128;       // 391
    const int spmm_grid = (NN + 7) / 8;

    // layer 1
    k_spmm<<<spmm_grid, 256>>>();
    k_gemm_tf32<<<gemm_grid, 256, GEMM_SMEM>>>(aggbuf, (const float4*)W1, b1, nsrc,
                                               (float2*)hbuf, NN);
    // layer 2
    k_spmm<<<spmm_grid, 256>>>();
    k_gemm_tf32<<<gemm_grid, 256, GEMM_SMEM>>>(aggbuf, (const float4*)W2, b2, nsrc,
                                               (float2*)hbuf, NN);
    // layer 3 -> d_out (no rowscale)
    k_spmm<<<spmm_grid, 256>>>();
    k_gemm_tf32<<<gemm_grid, 256, GEMM_SMEM>>>(aggbuf, (const float4*)W3, b3, nullptr,
                                               (float2*)outp, NN);
}